// round 13
// baseline (speedup 1.0000x reference)
#include <cuda_runtime.h>

// ---------------------------------------------------------------------------
// LIF scan, block-parallel with warm-up reconvergence. Round 12.
//
//   i_t = LK_I * i_{t-1} + w * x_t
//   v_t = LK_V * v_{t-1} * (1 - s_{t-1}) + i_t
//   s_t = (v_t > 1)
//
// 131072 chains x 64 steps, WARMUP=128 (validated floor: 96 flips ~33 spikes).
// Round-12 focus: hide the per-group x-gather DRAM latency with a cp.async
// one-group-deep pipeline. Smem row split: x words [0..32), state staging
// [32..56) (8-step flush cadence) -> prefetch of group g+1 overlaps compute
// and flush of group g with zero region conflicts. RS=60 conflict-free.
// ---------------------------------------------------------------------------

#define L_CHAIN  64
#define WARMUP  128
#define GSTEP    32
#define NG        6     // (L_CHAIN + WARMUP) / GSTEP
#define GSKIP     4     // WARMUP / GSTEP
#define WPB       2     // warps per block
#define RS       60     // row words: x [0..32), staging [32..56); CF banking

__device__ __forceinline__ void cp_async16(float* dst, const float* src) {
    unsigned d = (unsigned)__cvta_generic_to_shared(dst);
    asm volatile("cp.async.cg.shared.global [%0], [%1], 16;\n"
                 :: "r"(d), "l"(src));
}
__device__ __forceinline__ void cp_commit() {
    asm volatile("cp.async.commit_group;\n");
}
__device__ __forceinline__ void cp_wait0() {
    asm volatile("cp.async.wait_group 0;\n" ::: "memory");
}

__global__ __launch_bounds__(WPB * 32, 14)
void lif_scan_kernel(const float* __restrict__ x,
                     const float* __restrict__ st0,
                     const float* __restrict__ wptr,
                     float* __restrict__ out,
                     int T, int writeStates)
{
    __shared__ float smem[WPB][32][RS];            // 15360 B static

    const float w    = __ldg(wptr);
    const float LK_I = (float)(1.0 - 1.0 / 7.0);   // 0.857142857...
    const float LK_V = (float)(1.0 - 1.0 / 10.0);  // 0.9

    const int lane      = threadIdx.x & 31;
    const int warp      = threadIdx.x >> 5;
    const int chainbase = (blockIdx.x * WPB + warp) * 32;
    const int chain     = chainbase + lane;

    float* tw   = &smem[warp][0][0];
    float* trow = tw + lane * RS;

    float v, cur;
    bool  p;
    if (chain == 0) {
        float s0 = st0[0]; v = st0[1]; cur = st0[2]; p = (s0 != 0.0f);
    } else {
        v = 0.0f; cur = 0.0f; p = false;
    }
    const int gskip = (chain == 0) ? GSKIP : 0;    // chain 0: no warmup

    const int csel = lane >> 3;    // chain sub-index within gather/flush instr
    const int gq   = lane & 7;     // float4 index within a 32-float slice

    float* __restrict__ outO = out;        // outputs: [T]
    float* __restrict__ outS = out + T;    // states:  [T][3]

    // ---- prefetch group 0's x (async, GMEM -> SMEM, no register transit) ----
    #pragma unroll
    for (int j = 0; j < 8; j++) {
        int c = 4 * j + csel;
        int o = (chainbase + c) * L_CHAIN + (0 - GSKIP) * GSTEP + gq * 4;
        if (o < 0) o = 0;              // chains 0/1 truncated warmup only
        cp_async16(tw + c * RS + gq * 4, x + o);
    }
    cp_commit();

    for (int g = 0; g < NG; g++) {
        cp_wait0();                    // this group's x has landed
        __syncwarp();

        // ---- each lane loads its own 32 x values into registers ----
        float xa[32];
        #pragma unroll
        for (int k8 = 0; k8 < 8; k8++) {
            float4 val = *(const float4*)(trow + k8 * 4);
            xa[4 * k8 + 0] = val.x;
            xa[4 * k8 + 1] = val.y;
            xa[4 * k8 + 2] = val.z;
            xa[4 * k8 + 3] = val.w;
        }
        __syncwarp();                  // all lanes done reading x words

        // ---- issue next group's prefetch; overlaps compute + flush below ----
        if (g + 1 < NG) {
            #pragma unroll
            for (int j = 0; j < 8; j++) {
                int c = 4 * j + csel;
                int o = (chainbase + c) * L_CHAIN
                      + (g + 1 - GSKIP) * GSTEP + gq * 4;
                if (o < 0) o = 0;
                cp_async16(tw + c * RS + gq * 4, x + o);
            }
            cp_commit();
        }

        const bool mainG = (g >= GSKIP);           // warp-uniform
        const int  gm    = g - GSKIP;
        unsigned   sbits = 0;

        // ---- four sub-blocks of 8 steps; states staged+flushed per sub ----
        #pragma unroll
        for (int sf = 0; sf < 4; sf++) {
            if (mainG) __syncwarp();   // staging area free (prev readers done)

            if (g >= gskip) {          // divergent only in warmup groups
                #pragma unroll
                for (int kb = 0; kb < 2; kb++) {
                    float sv[4], vv[4], cv[4];
                    #pragma unroll
                    for (int u = 0; u < 4; u++) {
                        int k = sf * 8 + kb * 4 + u;
                        cur = fmaf(LK_I, cur, w * xa[k]);
                        float vn = fmaf(LK_V, v, cur);
                        v  = p ? cur : vn;        // reset-by-previous-spike
                        p  = (v > 1.0f);
                        sv[u] = p ? 1.0f : 0.0f;
                        vv[u] = v;
                        cv[u] = cur;
                        sbits |= (p ? 1u : 0u) << k;
                    }
                    if (mainG && writeStates) {
                        // interleaved [t][3]: staging words 32 + 12kb + [0,12)
                        float4 A = make_float4(sv[0], vv[0], cv[0], sv[1]);
                        float4 B = make_float4(vv[1], cv[1], sv[2], vv[2]);
                        float4 C = make_float4(cv[2], sv[3], vv[3], cv[3]);
                        *(float4*)(trow + 32 + 12 * kb + 0) = A;
                        *(float4*)(trow + 32 + 12 * kb + 4) = B;
                        *(float4*)(trow + 32 + 12 * kb + 8) = C;
                    }
                }
            }

            // ---- flush this sub-block's states (warp-uniform) ----
            if (mainG && writeStates) {
                __syncwarp();
                float* gsf = outS + chainbase * (3 * L_CHAIN)
                           + gm * (3 * GSTEP) + sf * 24;
                #pragma unroll
                for (int j = 0; j < 8; j++) {
                    if (gq < 6) {
                        int c = 4 * j + csel;
                        float4 val = *(float4*)(tw + c * RS + 32 + gq * 4);
                        __stcs((float4*)(gsf + c * (3 * L_CHAIN) + gq * 4),
                               val);
                    }
                }
            }
        }

        // ---- flush outputs: spike bits via shuffle, no SMEM ----
        if (mainG) {
            float* go = outO + chainbase * L_CHAIN + gm * GSTEP;
            #pragma unroll
            for (int j = 0; j < 8; j++) {
                int c = 4 * j + csel;
                unsigned bits = __shfl_sync(0xffffffffu, sbits, c);
                int b0 = 4 * gq;
                float4 f;
                f.x = ((bits >> (b0 + 0)) & 1u) ? 1.0f : 0.0f;
                f.y = ((bits >> (b0 + 1)) & 1u) ? 1.0f : 0.0f;
                f.z = ((bits >> (b0 + 2)) & 1u) ? 1.0f : 0.0f;
                f.w = ((bits >> (b0 + 3)) & 1u) ? 1.0f : 0.0f;
                __stcs((float4*)(go + c * L_CHAIN + gq * 4), f);
            }
        }
    }
}

// ---------------------------------------------------------------------------
// Fallback: fully sequential scan (any T).
// ---------------------------------------------------------------------------
__global__ void lif_scan_seq_kernel(const float* __restrict__ x,
                                    const float* __restrict__ st0,
                                    const float* __restrict__ wptr,
                                    float* __restrict__ out,
                                    int T, int writeStates)
{
    if (blockIdx.x != 0 || threadIdx.x != 0) return;
    const float w    = wptr[0];
    const float LK_I = (float)(1.0 - 1.0 / 7.0);
    const float LK_V = (float)(1.0 - 1.0 / 10.0);
    float s = st0[0], v = st0[1], cur = st0[2];
    float* outO = out;
    float* outS = out + T;
    for (int t = 0; t < T; t++) {
        cur = fmaf(LK_I, cur, w * x[t]);
        float lv = (s != 0.0f) ? 0.0f : LK_V;
        v = fmaf(lv, v, cur);
        s = (v > 1.0f) ? 1.0f : 0.0f;
        outO[t] = s;
        if (writeStates) {
            outS[3 * t + 0] = s;
            outS[3 * t + 1] = v;
            outS[3 * t + 2] = cur;
        }
    }
}

extern "C" void kernel_launch(void* const* d_in, const int* in_sizes, int n_in,
                              void* d_out, int out_size)
{
    const float* x  = (const float*)d_in[0];
    const float* st = (const float*)d_in[1];
    const float* wt = (const float*)d_in[2];
    float*       o  = (float*)d_out;

    const int T = in_sizes[0];
    const int writeStates = (out_size >= 4 * T) ? 1 : 0;

    const int chainsPerBlock = WPB * 32;                 // 64
    if (T >= L_CHAIN && (T % (L_CHAIN * chainsPerBlock)) == 0) {
        const int nchains = T / L_CHAIN;                 // 131072
        const int grid    = nchains / chainsPerBlock;    // 2048
        lif_scan_kernel<<<grid, chainsPerBlock>>>(x, st, wt, o, T, writeStates);
    } else {
        lif_scan_seq_kernel<<<1, 1>>>(x, st, wt, o, T, writeStates);
    }
}